// round 17
// baseline (speedup 1.0000x reference)
#include <cuda_runtime.h>
#include <cuda_fp16.h>
#include <cstdint>

// ---------------- problem constants ----------------
#define Bz   2
#define Nn   2048
#define Tt   256
#define Cc   1024
#define Hh   4096
#define Ss   2304          // N + T
#define HEADS 16
#define Dd   64

// ---------------- scratch (no allocation allowed) ----------------
__device__ float  g_m[Bz * 6 * Cc];                  // adaLN modulation vectors
__device__ __half g_qkvh[(long)Bz * Ss * 3 * Cc];    // qkv (fp16)
__device__ __half g_wTh[20971520];                   // transposed fp16 weights [N][K]
__device__ __half g_jh[(long)Bz * Ss * Cc];          // fp16: joint / x2,c2
__device__ __half g_ah[(long)Bz * Ss * Cc];          // fp16: attention out
__device__ __half g_hid16[(long)Bz * Ss * Hh];       // fp16: MLP hidden (x + cond rows)

// offsets into g_wTh (halves)
#define WT_QKV  0L
#define WT_PROJ 3145728L
#define WT_S1   4194304L
#define WT_S2   8388608L
#define WT_D1   12582912L
#define WT_D2   16777216L

// ---------------- activations ----------------
template<int ACT>
__device__ __forceinline__ float act_fn(float x) {
    if (ACT == 1) { // gelu tanh approx
        float x3 = x * x * x;
        return 0.5f * x * (1.f + tanhf(0.7978845608028654f * (x + 0.044715f * x3)));
    }
    if (ACT == 2) { // silu
        return x / (1.f + __expf(-x));
    }
    return x;
}

__device__ __forceinline__ void mma_f16(float* d,
                                        const uint32_t* a, const uint32_t* b) {
    asm volatile(
        "mma.sync.aligned.m16n8k16.row.col.f32.f16.f16.f32 "
        "{%0,%1,%2,%3}, {%4,%5,%6,%7}, {%8,%9}, {%0,%1,%2,%3};\n"
        : "+f"(d[0]), "+f"(d[1]), "+f"(d[2]), "+f"(d[3])
        : "r"(a[0]), "r"(a[1]), "r"(a[2]), "r"(a[3]), "r"(b[0]), "r"(b[1]));
}

__device__ __forceinline__ void cp_async16(uint32_t smem_dst, const void* gsrc) {
    asm volatile("cp.async.ca.shared.global [%0], [%1], 16;\n"
                 :: "r"(smem_dst), "l"(gsrc));
}

// ---------------- weight transpose + cvt: out[N][K] = (half)in[K][N] ----------------
__global__ void transpose_cvt_kernel(const float* __restrict__ in, __half* __restrict__ out,
                                     int K, int N) {
    __shared__ float t[64][65];
    int n0 = blockIdx.x * 64, k0 = blockIdx.y * 64;
    int tid = threadIdx.x;   // 256
#pragma unroll
    for (int i = 0; i < 8; i++) {
        int idx = tid + i * 256;
        int kr = idx >> 5;
        int nc = (idx & 31) * 2;
        float2 v = *(const float2*)(in + (long)(k0 + kr) * N + n0 + nc);
        t[nc][kr]     = v.x;
        t[nc + 1][kr] = v.y;
    }
    __syncthreads();
#pragma unroll
    for (int i = 0; i < 8; i++) {
        int idx = tid + i * 256;
        int nr = idx >> 5;
        int kc = (idx & 31) * 2;
        __half2 h = __floats2half2_rn(t[nr][kc], t[nr][kc + 1]);
        *(__half2*)(out + (long)(n0 + nr) * K + k0 + kc) = h;
    }
}

// ---------------- adaLN: m = silu(mod) @ w_adaln + b ----------------
__global__ void adaln_kernel(const float* __restrict__ mod,
                             const float* __restrict__ w,
                             const float* __restrict__ bias,
                             float* __restrict__ mout) {
    int b = blockIdx.y;
    int j = blockIdx.x * 256 + threadIdx.x;   // < 6144
    __shared__ float sm[Cc];
    for (int i = threadIdx.x; i < Cc; i += 256) {
        float v = mod[b * Cc + i];
        sm[i] = v / (1.f + __expf(-v));
    }
    __syncthreads();
    float acc = bias[j];
    for (int k = 0; k < Cc; k++) acc += sm[k] * w[(long)k * (6 * Cc) + j];
    mout[b * 6 * Cc + j] = acc;
}

// ---------------- LN + modulate -> fp16 out ----------------
__global__ void ln_mod_h_kernel(const float* __restrict__ in, __half* __restrict__ out,
                                const float* __restrict__ m, int rowsPerBatch,
                                int shOff, int scOff,
                                long outBatchStride, int outRowOff) {
    int row = blockIdx.x;
    int b = row / rowsPerBatch;
    int r = row - b * rowsPerBatch;
    const float* xi = in + (long)row * Cc;
    float v[4]; float s = 0.f, s2 = 0.f;
#pragma unroll
    for (int i = 0; i < 4; i++) {
        v[i] = xi[threadIdx.x + 256 * i];
        s += v[i]; s2 += v[i] * v[i];
    }
    __shared__ float rs[256], rs2[256];
    rs[threadIdx.x] = s; rs2[threadIdx.x] = s2;
    __syncthreads();
    for (int off = 128; off > 0; off >>= 1) {
        if (threadIdx.x < off) {
            rs[threadIdx.x]  += rs[threadIdx.x + off];
            rs2[threadIdx.x] += rs2[threadIdx.x + off];
        }
        __syncthreads();
    }
    float mu   = rs[0] * (1.f / (float)Cc);
    float var  = rs2[0] * (1.f / (float)Cc) - mu * mu;
    float rstd = rsqrtf(var + 1e-6f);
    const float* mb = m + b * 6 * Cc;
    __half* po = out + (long)b * outBatchStride + (long)(outRowOff + r) * Cc;
#pragma unroll
    for (int i = 0; i < 4; i++) {
        int c = threadIdx.x + 256 * i;
        po[c] = __float2half((v[i] - mu) * rstd * (1.f + mb[scOff + c]) + mb[shOff + c]);
    }
}

// ---------------- FP16 tensor-core GEMM, 256x128 tile, fused epilogues ----------------
// 8 warps: 4 (M, 64 rows) x 2 (N, 64 cols). BK=32 halves, 3-stage cp.async, 1 CTA/SM.
// MODE 1: C[fp16] = acc + bias1                                 (qkv)
// MODE 2: C[fp16] = region1 ? gelu(acc+bias1) : silu(acc+bias2) (s1 | d1 merged)
// MODE 3: fp32 out{x,c} = base{x,c} + (acc+bias1)*g_msa          (proj)
// MODE 4: fp32 out{x,c} = out{x,c} + (acc+bias{1,2})*g_mlp       (s2 | d2 merged)
#define GH_ST 20
#define GA_STG (256 * GH_ST)           // A stage words
#define GB_STG (128 * GH_ST)           // B stage words
#define GEMMH_SMEM (3 * (GA_STG + GB_STG) * 4)   // 92160 B

template<int MODE>
__global__ __launch_bounds__(256)
void gemm_h2(const __half* __restrict__ A,
             const __half* __restrict__ BT1, const __half* __restrict__ BT2,
             const float* __restrict__ bias1, const float* __restrict__ bias2,
             void* __restrict__ out1, void* __restrict__ out2,
             const float* __restrict__ base1, const float* __restrict__ base2,
             const float* __restrict__ gmv, int gOff, int splitBlk,
             int M, int N, int K) {
    extern __shared__ uint32_t smg[];
    uint32_t* As = smg;                     // [3][256][20]
    uint32_t* Bs = smg + 3 * GA_STG;        // [3][128][20]

    int tid  = threadIdx.x;
    int warp = tid >> 5, lane = tid & 31;
    int lg   = lane >> 2, tig = lane & 3;
    int warpM = (warp >> 1) * 64;           // 0,64,128,192
    int warpN = (warp & 1) * 64;            // 0,64

    bool reg1 = (int)blockIdx.y < splitBlk;
    const __half* BTsel = reg1 ? BT1 : BT2;
    const float*  bsel  = reg1 ? bias1 : bias2;

    const __half* Ab = A + (long)blockIdx.y * 256 * K;
    const __half* Bb = BTsel + (long)blockIdx.x * 128 * K;

    float acc[4][8][4];
#pragma unroll
    for (int i = 0; i < 4; i++)
#pragma unroll
        for (int j = 0; j < 8; j++)
#pragma unroll
            for (int q = 0; q < 4; q++) acc[i][j][q] = 0.f;

    int nstages = K >> 5;

#define GH_FILL(s) do {                                                        \
        int buf_ = (s) % 3;                                                    \
        int k0_  = (s) << 5;                                                   \
        uint32_t* Ad = As + buf_ * GA_STG;                                     \
        uint32_t* Bd = Bs + buf_ * GB_STG;                                     \
        _Pragma("unroll")                                                      \
        for (int i_ = 0; i_ < 4; i_++) {   /* A: 1024 chunks */                \
            int c_ = tid + i_ * 256;                                           \
            int r_ = c_ >> 2, kc_ = c_ & 3;                                    \
            uint32_t da_ = (uint32_t)__cvta_generic_to_shared(Ad + r_ * GH_ST + kc_ * 4); \
            cp_async16(da_, Ab + (long)r_ * K + k0_ + kc_ * 8);                \
        }                                                                      \
        _Pragma("unroll")                                                      \
        for (int i_ = 0; i_ < 2; i_++) {   /* B: 512 chunks */                 \
            int c_ = tid + i_ * 256;                                           \
            int r_ = c_ >> 2, kc_ = c_ & 3;                                    \
            uint32_t db_ = (uint32_t)__cvta_generic_to_shared(Bd + r_ * GH_ST + kc_ * 4); \
            cp_async16(db_, Bb + (long)r_ * K + k0_ + kc_ * 8);                \
        }                                                                      \
        asm volatile("cp.async.commit_group;\n");                              \
    } while (0)

    GH_FILL(0);
    GH_FILL(1);

    for (int s = 0; s < nstages; s++) {
        if (s + 1 < nstages) asm volatile("cp.async.wait_group 1;\n");
        else                 asm volatile("cp.async.wait_group 0;\n");
        __syncthreads();
        if (s + 2 < nstages) GH_FILL(s + 2);

        uint32_t* Ac = As + (s % 3) * GA_STG;
        uint32_t* Bc = Bs + (s % 3) * GB_STG;
#pragma unroll
        for (int kk = 0; kk < 2; kk++) {
            uint32_t af[4][4], bf[8][2];
#pragma unroll
            for (int mi = 0; mi < 4; mi++) {
                int m = warpM + mi * 16 + lg;
                af[mi][0] = Ac[m * GH_ST + kk * 8 + tig];
                af[mi][1] = Ac[(m + 8) * GH_ST + kk * 8 + tig];
                af[mi][2] = Ac[m * GH_ST + kk * 8 + 4 + tig];
                af[mi][3] = Ac[(m + 8) * GH_ST + kk * 8 + 4 + tig];
            }
#pragma unroll
            for (int ni = 0; ni < 8; ni++) {
                int n = warpN + ni * 8 + lg;
                bf[ni][0] = Bc[n * GH_ST + kk * 8 + tig];
                bf[ni][1] = Bc[n * GH_ST + kk * 8 + 4 + tig];
            }
#pragma unroll
            for (int mi = 0; mi < 4; mi++)
#pragma unroll
                for (int ni = 0; ni < 8; ni++)
                    mma_f16(acc[mi][ni], af[mi], bf[ni]);
        }
    }
#undef GH_FILL

    // ------------- fused epilogues -------------
    int gRow0 = blockIdx.y * 256;
    int colBase = blockIdx.x * 128 + warpN;

    float* outp = nullptr;
    const float* basep = nullptr;
    const float* gvp = nullptr;
    if (MODE == 3) {
        int b = gRow0 / Ss;
        int rr0 = gRow0 - b * Ss;
        if (rr0 < Nn) {
            outp  = (float*)out1 + ((long)b * Nn + rr0) * Cc;
            basep = base1 + ((long)b * Nn + rr0) * Cc;
        } else {
            outp  = (float*)out2 + ((long)b * Tt + rr0 - Nn) * Cc;
            basep = base2 + ((long)b * Tt + rr0 - Nn) * Cc;
        }
        gvp = gmv + b * 6 * Cc + gOff;
    }
    if (MODE == 4) {
        if (reg1) {
            int b = gRow0 >> 11;                      // / Nn
            outp  = (float*)out1 + (long)gRow0 * Cc;
            basep = base1 + (long)gRow0 * Cc;
            gvp = gmv + b * 6 * Cc + gOff;
        } else {
            int rc0 = gRow0 - Bz * Nn;
            int b = rc0 >> 8;                         // / Tt
            outp  = (float*)out2 + (long)rc0 * Cc;
            basep = base2 + (long)rc0 * Cc;
            gvp = gmv + b * 6 * Cc + gOff;
        }
    }

#pragma unroll
    for (int mi = 0; mi < 4; mi++) {
#pragma unroll
        for (int ni = 0; ni < 8; ni++) {
            int rloc = warpM + mi * 16 + lg;
            int c0 = colBase + ni * 8 + tig * 2;
            float b0 = bsel[c0], b1 = bsel[c0 + 1];
            float v00 = acc[mi][ni][0] + b0;
            float v01 = acc[mi][ni][1] + b1;
            float v10 = acc[mi][ni][2] + b0;
            float v11 = acc[mi][ni][3] + b1;
            if (MODE == 1) {
                __half* C = (__half*)out1;
                long r0 = gRow0 + rloc;
                *(__half2*)(C + r0 * N + c0)       = __floats2half2_rn(v00, v01);
                *(__half2*)(C + (r0 + 8) * N + c0) = __floats2half2_rn(v10, v11);
            } else if (MODE == 2) {
                if (reg1) {
                    v00 = act_fn<1>(v00); v01 = act_fn<1>(v01);
                    v10 = act_fn<1>(v10); v11 = act_fn<1>(v11);
                } else {
                    v00 = act_fn<2>(v00); v01 = act_fn<2>(v01);
                    v10 = act_fn<2>(v10); v11 = act_fn<2>(v11);
                }
                __half* C = (__half*)out1;
                long r0 = gRow0 + rloc;
                *(__half2*)(C + r0 * N + c0)       = __floats2half2_rn(v00, v01);
                *(__half2*)(C + (r0 + 8) * N + c0) = __floats2half2_rn(v10, v11);
            } else {
                float g0 = gvp[c0], g1 = gvp[c0 + 1];
                float* p0 = outp + (long)rloc * Cc + c0;
                float* p1 = outp + (long)(rloc + 8) * Cc + c0;
                const float* q0 = basep + (long)rloc * Cc + c0;
                const float* q1 = basep + (long)(rloc + 8) * Cc + c0;
                p0[0] = q0[0] + v00 * g0;
                p0[1] = q0[1] + v01 * g1;
                p1[0] = q1[0] + v10 * g0;
                p1[1] = q1[1] + v11 * g1;
            }
        }
    }
}

// ---------------- FP16 flash attention, BR=128, BC=64, shuffle softmax (validated R14) ----------------
#define FH_ST 36
#define FA_SMEM (int)(((128 + 64 + 128) * FH_ST + 4 * 128 + 2 * 256) * 4)
__global__ __launch_bounds__(256, 2)
void flash_h_kernel(const __half* __restrict__ qkvh, __half* __restrict__ outp) {
    extern __shared__ uint32_t smu[];
    uint32_t* Qs = smu;                          // [128][FH_ST]
    uint32_t* Ks = Qs + 128 * FH_ST;             // [64][FH_ST]  K tile, then V^T tile
    uint32_t* Ph = Ks + 64 * FH_ST;              // [128][FH_ST] probs (packed half2)
    float* mrow  = (float*)(Ph + 128 * FH_ST);   // [128]
    float* lrow  = mrow + 128;
    float* crow  = lrow + 128;
    float* tmrow = crow + 128;
    float* pm    = tmrow + 128;                  // [2][128] partial max
    float* ps    = pm + 256;                     // [2][128] partial sum

    int bh = blockIdx.y;
    int b = bh >> 4, h = bh & 15;
    int q0 = blockIdx.x * 128;
    int tid = threadIdx.x;
    int lane = tid & 31, warp = tid >> 5;
    int g = lane >> 2, tig = lane & 3;
    int warpM = (warp >> 1) * 32;
    int wn = warp & 1;
    int warpN = wn * 32;

    const __half2 qsc = __float2half2_rn(0.125f);
    for (int idx = tid; idx < 1024; idx += 256) {
        int r = idx & 127, s4 = idx >> 7;
        uint4 v = *(const uint4*)(qkvh + (long)(b * Ss + q0 + r) * (3 * Cc) + h * Dd + s4 * 8);
        __half2* hv = (__half2*)&v;
        hv[0] = __hmul2(hv[0], qsc);
        hv[1] = __hmul2(hv[1], qsc);
        hv[2] = __hmul2(hv[2], qsc);
        hv[3] = __hmul2(hv[3], qsc);
        *(uint4*)&Qs[r * FH_ST + s4 * 4] = v;
    }
    if (tid < 128) { mrow[tid] = -1e30f; lrow[tid] = 0.f; }
    __syncthreads();

    float Oc[2][4][4] = {};

    for (int j0 = 0; j0 < Ss; j0 += 64) {
        for (int idx = tid; idx < 512; idx += 256) {
            int r = idx & 63, s4 = idx >> 6;
            uint4 v = *(const uint4*)(qkvh + (long)(b * Ss + j0 + r) * (3 * Cc) + Cc + h * Dd + s4 * 8);
            *(uint4*)&Ks[r * FH_ST + s4 * 4] = v;
        }
        __syncthreads();                                    // bar A

        float Sc[2][4][4];
#pragma unroll
        for (int mi = 0; mi < 2; mi++)
#pragma unroll
            for (int ni = 0; ni < 4; ni++)
#pragma unroll
                for (int q = 0; q < 4; q++) Sc[mi][ni][q] = 0.f;
#pragma unroll
        for (int ks = 0; ks < 4; ks++) {
            uint32_t af[2][4], bf[4][2];
#pragma unroll
            for (int mi = 0; mi < 2; mi++) {
                int m = warpM + mi * 16 + g;
                af[mi][0] = Qs[m * FH_ST + ks * 8 + tig];
                af[mi][1] = Qs[(m + 8) * FH_ST + ks * 8 + tig];
                af[mi][2] = Qs[m * FH_ST + ks * 8 + 4 + tig];
                af[mi][3] = Qs[(m + 8) * FH_ST + ks * 8 + 4 + tig];
            }
#pragma unroll
            for (int ni = 0; ni < 4; ni++) {
                int n = warpN + ni * 8 + g;
                bf[ni][0] = Ks[n * FH_ST + ks * 8 + tig];
                bf[ni][1] = Ks[n * FH_ST + ks * 8 + 4 + tig];
            }
#pragma unroll
            for (int mi = 0; mi < 2; mi++)
#pragma unroll
                for (int ni = 0; ni < 4; ni++)
                    mma_f16(Sc[mi][ni], af[mi], bf[ni]);
        }

#pragma unroll
        for (int mi = 0; mi < 2; mi++) {
#pragma unroll
            for (int hf = 0; hf < 2; hf++) {
                float v = -1e30f;
#pragma unroll
                for (int ni = 0; ni < 4; ni++)
                    v = fmaxf(v, fmaxf(Sc[mi][ni][hf * 2], Sc[mi][ni][hf * 2 + 1]));
                v = fmaxf(v, __shfl_xor_sync(0xffffffff, v, 1));
                v = fmaxf(v, __shfl_xor_sync(0xffffffff, v, 2));
                if (tig == 0)
                    pm[wn * 128 + warpM + mi * 16 + g + hf * 8] = v;
            }
        }
        __syncthreads();                                    // bar B
        if (wn == 0 && tig == 0) {
#pragma unroll
            for (int mi = 0; mi < 2; mi++)
#pragma unroll
                for (int hf = 0; hf < 2; hf++) {
                    int r = warpM + mi * 16 + g + hf * 8;
                    float tm = fmaxf(fmaxf(pm[r], pm[128 + r]), mrow[r]);
                    tmrow[r] = tm;
                    crow[r] = __expf(mrow[r] - tm);
                    mrow[r] = tm;
                }
        }
        __syncthreads();                                    // bar C

#pragma unroll
        for (int mi = 0; mi < 2; mi++) {
#pragma unroll
            for (int hf = 0; hf < 2; hf++) {
                int r = warpM + mi * 16 + g + hf * 8;
                float tm = tmrow[r];
                float s = 0.f;
#pragma unroll
                for (int ni = 0; ni < 4; ni++) {
                    float p0 = __expf(Sc[mi][ni][hf * 2] - tm);
                    float p1 = __expf(Sc[mi][ni][hf * 2 + 1] - tm);
                    s += p0 + p1;
                    __half2 hp = __floats2half2_rn(p0, p1);
                    Ph[r * FH_ST + wn * 16 + ni * 4 + tig] = *(uint32_t*)&hp;
                }
                s += __shfl_xor_sync(0xffffffff, s, 1);
                s += __shfl_xor_sync(0xffffffff, s, 2);
                if (tig == 0)
                    ps[wn * 128 + r] = s;
            }
        }

        {
            int c2 = tid & 31, i = tid >> 5;
            const __half* vb = qkvh + 2 * Cc + h * Dd + i * 8;
            uint4 lo = *(const uint4*)(vb + (long)(b * Ss + j0 + 2 * c2) * (3 * Cc));
            uint4 hi = *(const uint4*)(vb + (long)(b * Ss + j0 + 2 * c2 + 1) * (3 * Cc));
            const uint32_t* lw = (const uint32_t*)&lo;
            const uint32_t* hw = (const uint32_t*)&hi;
#pragma unroll
            for (int j = 0; j < 8; j++) {
                uint32_t w = __byte_perm(lw[j >> 1], hw[j >> 1], (j & 1) ? 0x7632 : 0x5410);
                Ks[(i * 8 + j) * FH_ST + c2] = w;
            }
        }
        __syncthreads();                                    // bar D

        if (wn == 0 && tig == 0) {
#pragma unroll
            for (int mi = 0; mi < 2; mi++)
#pragma unroll
                for (int hf = 0; hf < 2; hf++) {
                    int r = warpM + mi * 16 + g + hf * 8;
                    lrow[r] = lrow[r] * crow[r] + ps[r] + ps[128 + r];
                }
        }

#pragma unroll
        for (int mi = 0; mi < 2; mi++) {
            int m0 = warpM + mi * 16 + g;
            float cl = crow[m0], ch = crow[m0 + 8];
#pragma unroll
            for (int ni = 0; ni < 4; ni++) {
                Oc[mi][ni][0] *= cl; Oc[mi][ni][1] *= cl;
                Oc[mi][ni][2] *= ch; Oc[mi][ni][3] *= ch;
            }
        }

#pragma unroll
        for (int ks = 0; ks < 4; ks++) {
            uint32_t af[2][4], bf[4][2];
#pragma unroll
            for (int mi = 0; mi < 2; mi++) {
                int m = warpM + mi * 16 + g;
                af[mi][0] = Ph[m * FH_ST + ks * 8 + tig];
                af[mi][1] = Ph[(m + 8) * FH_ST + ks * 8 + tig];
                af[mi][2] = Ph[m * FH_ST + ks * 8 + 4 + tig];
                af[mi][3] = Ph[(m + 8) * FH_ST + ks * 8 + 4 + tig];
            }
#pragma unroll
            for (int ni = 0; ni < 4; ni++) {
                int n = warpN + ni * 8 + g;
                bf[ni][0] = Ks[n * FH_ST + ks * 8 + tig];
                bf[ni][1] = Ks[n * FH_ST + ks * 8 + 4 + tig];
            }
#pragma unroll
            for (int mi = 0; mi < 2; mi++)
#pragma unroll
                for (int ni = 0; ni < 4; ni++)
                    mma_f16(Oc[mi][ni], af[mi], bf[ni]);
        }
        __syncthreads();                                    // bar E
    }

#pragma unroll
    for (int mi = 0; mi < 2; mi++) {
        int m0 = warpM + mi * 16 + g;
        float inv0 = 1.f / lrow[m0];
        float inv1 = 1.f / lrow[m0 + 8];
#pragma unroll
        for (int ni = 0; ni < 4; ni++) {
            int n0 = warpN + ni * 8 + tig * 2;
            *(__half2*)(outp + (long)(b * Ss + q0 + m0) * Cc + h * Dd + n0) =
                __floats2half2_rn(Oc[mi][ni][0] * inv0, Oc[mi][ni][1] * inv0);
            *(__half2*)(outp + (long)(b * Ss + q0 + m0 + 8) * Cc + h * Dd + n0) =
                __floats2half2_rn(Oc[mi][ni][2] * inv1, Oc[mi][ni][3] * inv1);
        }
    }
}

// ---------------- launch ----------------
extern "C" void kernel_launch(void* const* d_in, const int* in_sizes, int n_in,
                              void* d_out, int out_size) {
    const float* x       = (const float*)d_in[0];
    const float* mod     = (const float*)d_in[1];
    const float* cond    = (const float*)d_in[2];
    const float* w_adaln = (const float*)d_in[3];
    const float* b_adaln = (const float*)d_in[4];
    const float* w_qkv   = (const float*)d_in[5];
    const float* b_qkv   = (const float*)d_in[6];
    const float* w_proj  = (const float*)d_in[7];
    const float* b_proj  = (const float*)d_in[8];
    const float* w_s1    = (const float*)d_in[9];
    const float* b_s1    = (const float*)d_in[10];
    const float* w_s2    = (const float*)d_in[11];
    const float* b_s2    = (const float*)d_in[12];
    const float* w_d1    = (const float*)d_in[13];
    const float* b_d1    = (const float*)d_in[14];
    const float* w_d2    = (const float*)d_in[15];
    const float* b_d2    = (const float*)d_in[16];

    float* outx = (float*)d_out;                         // [2,2048,1024]
    float* outc = outx + (long)Bz * Nn * Cc;             // [2,256,1024]

    float *gm;
    __half *gqkvh, *gwth, *gjh, *gah, *ghid;
    cudaGetSymbolAddress((void**)&gm,    g_m);
    cudaGetSymbolAddress((void**)&gqkvh, g_qkvh);
    cudaGetSymbolAddress((void**)&gwth,  g_wTh);
    cudaGetSymbolAddress((void**)&gjh,   g_jh);
    cudaGetSymbolAddress((void**)&gah,   g_ah);
    cudaGetSymbolAddress((void**)&ghid,  g_hid16);

    cudaFuncSetAttribute(flash_h_kernel, cudaFuncAttributeMaxDynamicSharedMemorySize, FA_SMEM);
    cudaFuncSetAttribute(gemm_h2<1>, cudaFuncAttributeMaxDynamicSharedMemorySize, GEMMH_SMEM);
    cudaFuncSetAttribute(gemm_h2<2>, cudaFuncAttributeMaxDynamicSharedMemorySize, GEMMH_SMEM);
    cudaFuncSetAttribute(gemm_h2<3>, cudaFuncAttributeMaxDynamicSharedMemorySize, GEMMH_SMEM);
    cudaFuncSetAttribute(gemm_h2<4>, cudaFuncAttributeMaxDynamicSharedMemorySize, GEMMH_SMEM);

    const long SC = (long)Ss * Cc;
    const long NC = (long)Nn * Cc;
    const long TC = (long)Tt * Cc;

    // 0. weight transposes + fp16 cvt
    transpose_cvt_kernel<<<dim3(3 * Cc / 64, Cc / 64), 256>>>(w_qkv,  gwth + WT_QKV,  Cc, 3 * Cc);
    transpose_cvt_kernel<<<dim3(Cc / 64, Cc / 64),     256>>>(w_proj, gwth + WT_PROJ, Cc, Cc);
    transpose_cvt_kernel<<<dim3(Hh / 64, Cc / 64),     256>>>(w_s1,   gwth + WT_S1,   Cc, Hh);
    transpose_cvt_kernel<<<dim3(Cc / 64, Hh / 64),     256>>>(w_s2,   gwth + WT_S2,   Hh, Cc);
    transpose_cvt_kernel<<<dim3(Hh / 64, Cc / 64),     256>>>(w_d1,   gwth + WT_D1,   Cc, Hh);
    transpose_cvt_kernel<<<dim3(Cc / 64, Hh / 64),     256>>>(w_d2,   gwth + WT_D2,   Hh, Cc);

    // 1. modulation vectors
    adaln_kernel<<<dim3(24, Bz), 256>>>(mod, w_adaln, b_adaln, gm);

    // 2. LN + msa modulate -> joint fp16 [B,S,C]
    ln_mod_h_kernel<<<Bz * Nn, 256>>>(x,    gjh, gm, Nn, 0, Cc, SC, 0);
    ln_mod_h_kernel<<<Bz * Tt, 256>>>(cond, gjh, gm, Tt, 0, Cc, SC, Nn);

    // 3. qkv (fp16 out): grid (3072/128, 4608/256)
    gemm_h2<1><<<dim3(24, 18), 256, GEMMH_SMEM>>>(
        gjh, gwth + WT_QKV, gwth + WT_QKV, b_qkv, b_qkv,
        gqkvh, nullptr, nullptr, nullptr, nullptr, 0, 18,
        Bz * Ss, 3 * Cc, Cc);

    // 4. attention
    flash_h_kernel<<<dim3(Ss / 128, Bz * HEADS), 256, FA_SMEM>>>(gqkvh, gah);

    // 5. proj + fused attn-residual: grid (8, 18) = 144 CTAs (1 wave)
    gemm_h2<3><<<dim3(8, 18), 256, GEMMH_SMEM>>>(
        gah, gwth + WT_PROJ, gwth + WT_PROJ, b_proj, b_proj,
        outx, outc, x, cond, gm, 2 * Cc, 18,
        Bz * Ss, Cc, Cc);

    // 6. LN + mlp modulate -> fp16 x2/c2
    __half* gx2 = gjh;
    __half* gc2 = gjh + (long)Bz * Nn * Cc;
    ln_mod_h_kernel<<<Bz * Nn, 256>>>(outx, gx2, gm, Nn, 3 * Cc, 4 * Cc, NC, 0);
    ln_mod_h_kernel<<<Bz * Tt, 256>>>(outc, gc2, gm, Tt, 3 * Cc, 4 * Cc, TC, 0);

    // 7. merged s1|d1 -> ghid fp16 (split at block 16 = row 4096)
    gemm_h2<2><<<dim3(32, 18), 256, GEMMH_SMEM>>>(
        gjh, gwth + WT_S1, gwth + WT_D1, b_s1, b_d1,
        ghid, nullptr, nullptr, nullptr, nullptr, 0, 16,
        Bz * Ss, Hh, Cc);

    // 8. merged s2|d2 + fused mlp-residual: grid (8, 18) = 144 CTAs
    gemm_h2<4><<<dim3(8, 18), 256, GEMMH_SMEM>>>(
        ghid, gwth + WT_S2, gwth + WT_D2, b_s2, b_d2,
        outx, outc, outx, outc, gm, 5 * Cc, 16,
        Bz * Ss, Cc, Hh);
}